// round 8
// baseline (speedup 1.0000x reference)
#include <cuda_runtime.h>

// TemporalViewModel: 24-step GRU over 65536 seqs (F=32, H=32) + proj 32->16.
//
// Register-blocked GEMM formulation. Per timestep: G = [x|h](64 seqs x 64k) @ W(64 x 128),
// outputs o: r[0,32) z[32,64) nx[64,96) nh[96,128). nx only uses the x half of K,
// nh only the h half.
// CTA = 128 threads; og = tid>>3 (out-group), sg = tid&7 (seq-group).
// Thread tile: 8 outs x 8 seqs (4 f32x2 pairs) -> 32 u64 accumulators (FFMA2).
//   og<8 : outs {r units og*4..+3} (full K) + {nx same units} (x half only)
//   og>=8: outs {z units (og-8)*4..+3} (full K) + {nh same units} (h half only)
// -> every thread does exactly 384 K-out products/step; all warps balanced.
// Epilogue: thread pair (og, og+8) holds {r,nx} / {z,nh} for the SAME units;
// each stages 2 of its 4 pairs to SMEM and consumes the other 2.
// NOTE: weight columns are indexed by og4 (0..95 global), but stage/h buffers
// are indexed by the true unit offset ou4 = og4 & 31.

#define TT   24
#define NSEQ 65536
#define NT   128

typedef unsigned long long u64;

__device__ __forceinline__ u64 pk(float lo, float hi){
    u64 r; asm("mov.b64 %0,{%1,%2};" : "=l"(r) : "f"(lo), "f"(hi)); return r;
}
__device__ __forceinline__ void upk(u64 v, float& lo, float& hi){
    asm("mov.b64 {%0,%1},%2;" : "=f"(lo), "=f"(hi) : "l"(v));
}
__device__ __forceinline__ void fma2(u64& d, u64 a, u64 b){
    asm("fma.rn.f32x2 %0,%1,%2,%0;" : "+l"(d) : "l"(a), "l"(b));
}
__device__ __forceinline__ float sigmf(float x){
    return __fdividef(1.0f, 1.0f + __expf(-x));
}
__device__ __forceinline__ float tanh_fast(float x){
    x = fminf(fmaxf(x, -15.0f), 15.0f);
    float e = __expf(2.0f * x);
    return (e - 1.0f) * __fdividef(1.0f, e + 1.0f);
}
__device__ __forceinline__ float gru_epi(float r, float z, float nx, float nh, float hold){
    float rv = sigmf(r), zv = sigmf(z);
    float n  = tanh_fast(fmaf(rv, nh, nx));
    return n + zv * (hold - n);
}

// SMEM layout in u64 units:
//   Wx  [32k][96o]  @0      dup(W_ih[o*32+k])           24576 B
//   Wh  [32k][96o]  @3072   dup(W_hh[o*32+k])           24576 B
//   bdup[128]       @6144   dup biases                   1024 B
//   xb  [32k][34]   @6272   x pairs [k][pair]            8704 B
//   hb  [32u][34]   @7360   h pairs [u][pair]            8704 B
//   stg [32p][66]   @8448   staged gates [p][slot0/1][u] 16896 B
//   swo float[512]  @10560  proj W                       2048 B
#define O_WX 0
#define O_WH 3072
#define O_BD 6144
#define O_XB 6272
#define O_HB 7360
#define O_SG 8448
#define PS   66
#define SMEM_BYTES (10560*8 + 2048)

#define LOADA(AB,kk) \
    ulonglong2 a01 = *(const ulonglong2*)((AB) + (kk)*34 + sg4); \
    ulonglong2 a23 = *(const ulonglong2*)((AB) + (kk)*34 + sg4 + 2);
#define LOADW(WB,kk) \
    const u64* wr_ = (WB) + (kk)*96 + og4; \
    ulonglong2 w01 = *(const ulonglong2*)(wr_); \
    ulonglong2 w23 = *(const ulonglong2*)(wr_ + 2);
#define LOADV(off) \
    ulonglong2 v01 = *(const ulonglong2*)(wr_ + (off)); \
    ulonglong2 v23 = *(const ulonglong2*)(wr_ + (off) + 2);
#define ROW4(aa,p) \
    fma2(acc[0][p],aa,w01.x); fma2(acc[1][p],aa,w01.y); \
    fma2(acc[2][p],aa,w23.x); fma2(acc[3][p],aa,w23.y);
#define ROW8(aa,p) ROW4(aa,p) \
    fma2(acc[4][p],aa,v01.x); fma2(acc[5][p],aa,v01.y); \
    fma2(acc[6][p],aa,v23.x); fma2(acc[7][p],aa,v23.y);
#define STEP8(AB,WB,voff,kk) { LOADA(AB,kk) LOADW(WB,kk) LOADV(voff) \
    ROW8(a01.x,0) ROW8(a01.y,1) ROW8(a23.x,2) ROW8(a23.y,3) }
#define STEP4(AB,WB,kk) { LOADA(AB,kk) LOADW(WB,kk) \
    ROW4(a01.x,0) ROW4(a01.y,1) ROW4(a23.x,2) ROW4(a23.y,3) }

#define PREFETCH(tt) { \
    size_t bse = ((size_t)(tt)*NSEQ + seqbase + s); \
    if (fh == 0){ const float4* q = (const float4*)(spat + bse*16); \
        pf0 = q[0]; pf1 = q[1]; pf2 = q[2]; pf3 = q[3]; } \
    else { const float4* qm = (const float4*)(met + bse*8); \
           const float4* qc = (const float4*)(ctx + bse*8); \
        pf0 = qm[0]; pf1 = qm[1]; pf2 = qc[0]; pf3 = qc[1]; } }

extern "C" __global__ void __launch_bounds__(NT, 2)
gru_kernel(const float* __restrict__ spat, const float* __restrict__ met,
           const float* __restrict__ ctx,
           const float* __restrict__ W_ih, const float* __restrict__ W_hh,
           const float* __restrict__ b_ih, const float* __restrict__ b_hh,
           const float* __restrict__ Wo, float* __restrict__ out)
{
    extern __shared__ u64 sm[];
    float* swo = (float*)(sm + 10560);

    const int tid = threadIdx.x;
    const int og  = tid >> 3, sg = tid & 7;
    const int og4 = og * 4,  sg4 = sg * 4;
    const int ou4 = og4 & 31;          // true hidden-unit offset (0..28)
    const int seqbase = blockIdx.x * 64;

    // ---- prologue staging ----
    for (int i = tid; i < 3072; i += NT){
        int k = i / 96, o = i % 96;
        float a = W_ih[o*32 + k], b = W_hh[o*32 + k];
        sm[O_WX + i] = pk(a, a);
        sm[O_WH + i] = pk(b, b);
    }
    for (int i = tid; i < 128; i += NT){
        float v = (i < 64) ? (b_ih[i] + b_hh[i]) : (i < 96 ? b_ih[i] : b_hh[i-32]);
        sm[O_BD + i] = pk(v, v);
    }
    for (int i = tid; i < 1088; i += NT) sm[O_HB + i] = 0ULL;
    for (int i = tid; i < 512;  i += NT) swo[i] = Wo[i];

    // ---- x prefetch (t = 0) ----
    const int s = tid & 63;          // sequence within CTA this thread loads
    const int fh = tid >> 6;         // 0: spat(16f), 1: met+ctx(8f+8f)
    const int kb = fh * 16;
    float4 pf0, pf1, pf2, pf3;
    PREFETCH(0)
    __syncthreads();

    u64 b1[4], b2[4];
    #pragma unroll
    for (int j = 0; j < 4; j++){ b1[j] = sm[O_BD + og4 + j]; b2[j] = sm[O_BD + 64 + og4 + j]; }

    float* xw = (float*)(sm + O_XB);

    for (int t = 0; t < TT; t++){
        // ---- write this timestep's x into xb [k][pair-packed] ----
        {
            float c4[16];
            *(float4*)(c4+0)  = pf0; *(float4*)(c4+4)  = pf1;
            *(float4*)(c4+8)  = pf2; *(float4*)(c4+12) = pf3;
            #pragma unroll
            for (int k = 0; k < 16; k++)
                xw[(kb + k)*68 + s] = c4[k];   // word (k*34+pair)*2+half == k*68+s
        }
        __syncthreads();                        // xb + hb ready; stg free
        if (t + 1 < TT) PREFETCH(t+1)

        // ---- GEMM: 8 outs x 4 pairs, bias-initialized accumulators ----
        u64 acc[8][4];
        #pragma unroll
        for (int j = 0; j < 4; j++){
            #pragma unroll
            for (int p = 0; p < 4; p++){ acc[j][p] = b1[j]; acc[4+j][p] = b2[j]; }
        }
        if (og < 8){
            #pragma unroll 4
            for (int k = 0; k < 32; k++) STEP8(sm + O_XB, sm + O_WX, 64, k)   // r + nx
            #pragma unroll 4
            for (int k = 0; k < 32; k++) STEP4(sm + O_HB, sm + O_WH, k)       // r (h half)
        } else {
            #pragma unroll 4
            for (int k = 0; k < 32; k++) STEP4(sm + O_XB, sm + O_WX, k)       // z (x half)
            #pragma unroll 4
            for (int k = 0; k < 32; k++) STEP8(sm + O_HB, sm + O_WH, 32, k)   // z + nh
        }

        // ---- stage foreign pairs: og<8 stages pairs +2,+3; og>=8 stages +0,+1 ----
        {
            const int pb = (og < 8) ? 2 : 0;
            #pragma unroll
            for (int pp = 0; pp < 2; pp++){
                int lp = pb + pp;
                u64* spw = sm + O_SG + (size_t)(sg4 + lp) * PS;
                ulonglong2 t0; t0.x = acc[0][lp]; t0.y = acc[1][lp];
                ulonglong2 t1; t1.x = acc[2][lp]; t1.y = acc[3][lp];
                ulonglong2 t2; t2.x = acc[4][lp]; t2.y = acc[5][lp];
                ulonglong2 t3; t3.x = acc[6][lp]; t3.y = acc[7][lp];
                *(ulonglong2*)(spw + ou4)          = t0;
                *(ulonglong2*)(spw + ou4 + 2)      = t1;
                *(ulonglong2*)(spw + 32 + ou4)     = t2;
                *(ulonglong2*)(spw + 32 + ou4 + 2) = t3;
            }
        }
        __syncthreads();

        // ---- epilogue: consume own pairs (og<8: +0,+1 ; og>=8: +2,+3) ----
        {
            const int cb = (og < 8) ? 0 : 2;
            u64* hbw = sm + O_HB;
            #pragma unroll
            for (int pp = 0; pp < 2; pp++){
                int lp = cb + pp, p = sg4 + lp;
                const u64* spr = sm + O_SG + (size_t)p * PS;
                #pragma unroll
                for (int j = 0; j < 4; j++){
                    u64 s0 = spr[ou4 + j];         // staged slot0 (z for A / r for B)
                    u64 s1 = spr[32 + ou4 + j];    // staged slot1 (nh for A / nx for B)
                    u64 ho = hbw[(ou4 + j)*34 + p];
                    float g1a,g1b,g2a,g2b,sa0,sb0,sa1,sb1,ha,hc,hn0,hn1;
                    upk(acc[j][lp],   g1a, g1b);
                    upk(acc[4+j][lp], g2a, g2b);
                    upk(s0, sa0, sb0); upk(s1, sa1, sb1); upk(ho, ha, hc);
                    if (og < 8){   // mine: r=G1, nx=G2 ; staged: z, nh
                        hn0 = gru_epi(g1a, sa0, g2a, sa1, ha);
                        hn1 = gru_epi(g1b, sb0, g2b, sb1, hc);
                    } else {       // mine: z=G1, nh=G2 ; staged: r, nx
                        hn0 = gru_epi(sa0, g1a, sa1, g2a, ha);
                        hn1 = gru_epi(sb0, g1b, sb1, g2b, hc);
                    }
                    hbw[(ou4 + j)*34 + p] = pk(hn0, hn1);
                }
            }
        }
    }
    __syncthreads();

    // ---- output projection: out[seq][16] = h @ Wo ----
    {
        int ss = tid >> 1, jo = (tid & 1) * 8;
        const float* hw = (const float*)(sm + O_HB);
        float o[8];
        #pragma unroll
        for (int j = 0; j < 8; j++) o[j] = 0.0f;
        #pragma unroll 8
        for (int u = 0; u < 32; u++){
            float hv = hw[u*68 + ss];
            #pragma unroll
            for (int j = 0; j < 8; j++) o[j] = fmaf(hv, swo[u*16 + jo + j], o[j]);
        }
        float* op = out + ((size_t)(seqbase + ss))*16 + jo;
        #pragma unroll
        for (int j = 0; j < 8; j++) op[j] = o[j];
    }
}

extern "C" void kernel_launch(void* const* d_in, const int* in_sizes, int n_in,
                              void* d_out, int out_size)
{
    const float* spat = (const float*)d_in[0];
    const float* met  = (const float*)d_in[1];
    const float* ctx  = (const float*)d_in[2];
    const float* W_ih = (const float*)d_in[3];
    const float* W_hh = (const float*)d_in[4];
    const float* b_ih = (const float*)d_in[5];
    const float* b_hh = (const float*)d_in[6];
    const float* Wo   = (const float*)d_in[7];
    float* out = (float*)d_out;

    cudaFuncSetAttribute(gru_kernel, cudaFuncAttributeMaxDynamicSharedMemorySize, SMEM_BYTES);
    dim3 grid(NSEQ / 64);   // 1024 CTAs x 128 threads, 64 seqs/CTA
    gru_kernel<<<grid, NT, SMEM_BYTES>>>(spat, met, ctx, W_ih, W_hh, b_ih, b_hh, Wo, out);
}

// round 9
// speedup vs baseline: 2.7713x; 2.7713x over previous
#include <cuda_runtime.h>
#include <cuda_bf16.h>

// TemporalViewModel GRU via bf16 split-precision tensor-core GEMM.
// Per step: A=[x|h] (64 seqs x 64 K) @ B (64 x 128), cols gate-interleaved
// (col = unit*4 + gate; gate 0=r,1=z,2=nx(k<32 only),3=nh(k>=32 only)).
// Split precision: w = hi + lo (bf16); D = Ahi*Bhi + Alo*Bhi + Ahi*Blo (fp32 acc).
// Warp = one m16 seq tile; 16 n-tiles x 4 k-chunks x 3 passes = 192 mma/warp/step.
// B-fragments precomputed into SMEM in mma fragment order (W is constant).

#define TT   24
#define NSEQ 65536
#define NT   128
#define RP   72          // A row pitch (bf16 elems); 144 B -> conflict-free frags

// SMEM byte offsets
#define OFF_AH   0                    // Ahi [64][RP] bf16   9216 B
#define OFF_AL   9216                 // Alo                 9216 B
#define OFF_BFH  18432                // B frags hi, 4096 u32 = 16384 B
#define OFF_BFL  34816                // B frags lo          16384 B
#define OFF_BIAS 51200                // 32 units x float4     512 B
#define OFF_WO   51712                // proj W 32x16 f32     2048 B
#define SMEM_BYTES 53760

__device__ __forceinline__ float sigmf(float x){
    return __fdividef(1.0f, 1.0f + __expf(-x));
}
__device__ __forceinline__ float tanh_fast(float x){
    x = fminf(fmaxf(x, -15.0f), 15.0f);
    float e = __expf(2.0f * x);
    return (e - 1.0f) * __fdividef(1.0f, e + 1.0f);
}
__device__ __forceinline__ unsigned pk_bf2(float a, float b){
    __nv_bfloat162 t = __floats2bfloat162_rn(a, b);
    return *(unsigned*)&t;
}
// weight for B column (unit u, gate gg) at K-row k (k<32: x/W_ih, k>=32: h/W_hh)
__device__ __forceinline__ float wlook(int k, int u, int gg,
        const float* __restrict__ Wih, const float* __restrict__ Whh){
    if (k < 32){
        if (gg == 3) return 0.0f;
        return Wih[(gg*32 + u)*32 + k];          // gg 0,1,2 -> rows u,32+u,64+u
    } else {
        if (gg == 2) return 0.0f;
        int row = (gg == 3) ? (64 + u) : (gg*32 + u);
        return Whh[row*32 + (k - 32)];
    }
}

#define MMA(d0,d1,d2,d3,a0,a1,a2,a3,b0,b1) \
  asm volatile("mma.sync.aligned.m16n8k16.row.col.f32.bf16.bf16.f32 " \
    "{%0,%1,%2,%3}, {%4,%5,%6,%7}, {%8,%9}, {%0,%1,%2,%3};" \
    : "+f"(d0),"+f"(d1),"+f"(d2),"+f"(d3) \
    : "r"(a0),"r"(a1),"r"(a2),"r"(a3),"r"(b0),"r"(b1))

#define PREF(tt) { size_t b_ = ((size_t)(tt)*NSEQ + seqbase + s); \
    if (half == 0){ const float4* q = (const float4*)(spat + b_*16); \
      pf0=q[0]; pf1=q[1]; pf2=q[2]; pf3=q[3]; } \
    else { const float4* qm = (const float4*)(met + b_*8); \
           const float4* qc = (const float4*)(ctx + b_*8); \
      pf0=qm[0]; pf1=qm[1]; pf2=qc[0]; pf3=qc[1]; } }

#define XSTORE { float c4[16]; \
    *(float4*)(c4+0)=pf0; *(float4*)(c4+4)=pf1; *(float4*)(c4+8)=pf2; *(float4*)(c4+12)=pf3; \
    _Pragma("unroll") \
    for (int q = 0; q < 8; q++){ \
      float v0 = c4[2*q], v1 = c4[2*q+1]; \
      float l0 = v0 - __bfloat162float(__float2bfloat16(v0)); \
      float l1 = v1 - __bfloat162float(__float2bfloat16(v1)); \
      *(unsigned*)&Ah[s*RP + kb + 2*q] = pk_bf2(v0, v1); \
      *(unsigned*)&Al[s*RP + kb + 2*q] = pk_bf2(l0, l1); } }

extern "C" __global__ void __launch_bounds__(NT, 4)
gru_tc(const float* __restrict__ spat, const float* __restrict__ met,
       const float* __restrict__ ctx,
       const float* __restrict__ W_ih, const float* __restrict__ W_hh,
       const float* __restrict__ b_ih, const float* __restrict__ b_hh,
       const float* __restrict__ Wo, float* __restrict__ out)
{
    extern __shared__ char sm[];
    __nv_bfloat16* Ah = (__nv_bfloat16*)(sm + OFF_AH);
    __nv_bfloat16* Al = (__nv_bfloat16*)(sm + OFF_AL);
    unsigned* BfH = (unsigned*)(sm + OFF_BFH);
    unsigned* BfL = (unsigned*)(sm + OFF_BFL);
    float* sbias = (float*)(sm + OFF_BIAS);
    float* swo   = (float*)(sm + OFF_WO);

    const int tid = threadIdx.x;
    const int lane = tid & 31, wrp = tid >> 5;
    const int g = lane >> 2, tig = lane & 3;
    const int R = wrp * 16;
    const int seqbase = blockIdx.x * 64;

    // ---- prologue ----
    { unsigned* az = (unsigned*)sm;                     // zero Ahi+Alo (18432 B)
      for (int i = tid; i < 4608; i += NT) az[i] = 0; }

    // B fragments (hi & lo), laid out exactly as the mainloop reads them:
    // slot e = ((kc*16 + j)*32 + lane)*2 + reg
    for (int e = tid; e < 4096; e += NT){
        int reg = e & 1, ln = (e >> 1) & 31, j = (e >> 6) & 15, kc = e >> 10;
        int tg = ln & 3, cg = ln >> 2;
        int col = j*8 + cg;
        int u = col >> 2, gg = col & 3;
        int k0 = kc*16 + 2*tg + 8*reg;
        float w0 = wlook(k0,   u, gg, W_ih, W_hh);
        float w1 = wlook(k0+1, u, gg, W_ih, W_hh);
        float h0 = __bfloat162float(__float2bfloat16(w0));
        float h1 = __bfloat162float(__float2bfloat16(w1));
        BfH[e] = pk_bf2(w0, w1);
        BfL[e] = pk_bf2(w0 - h0, w1 - h1);
    }
    if (tid < 32){
        sbias[tid*4+0] = b_ih[tid]    + b_hh[tid];      // r
        sbias[tid*4+1] = b_ih[32+tid] + b_hh[32+tid];   // z
        sbias[tid*4+2] = b_ih[64+tid];                  // nx
        sbias[tid*4+3] = b_hh[64+tid];                  // nh
    }
    for (int i = tid; i < 512; i += NT) swo[i] = Wo[i];

    // x(0) load + store
    const int s = tid >> 1, half = tid & 1, kb = half * 16;
    float4 pf0, pf1, pf2, pf3;
    PREF(0); XSTORE;

    float hreg[16];
    #pragma unroll
    for (int j = 0; j < 16; j++) hreg[j] = 0.0f;
    __syncthreads();

    const int even = !(lane & 1);
    const int r0 = R + g, r1 = R + g + 8;
    const int uc = tig >> 1;
    const int hrow = even ? r0 : r1;

    for (int t = 0; t < TT; t++){
        // ---- A fragments (x hi/lo + h hi/lo) ----
        unsigned ah[4][4], al[4][4];
        #pragma unroll
        for (int kc = 0; kc < 4; kc++){
            int c0 = kc*16 + 2*tig, c1 = c0 + 8;
            ah[kc][0] = *(const unsigned*)&Ah[r0*RP + c0];
            ah[kc][1] = *(const unsigned*)&Ah[r1*RP + c0];
            ah[kc][2] = *(const unsigned*)&Ah[r0*RP + c1];
            ah[kc][3] = *(const unsigned*)&Ah[r1*RP + c1];
            al[kc][0] = *(const unsigned*)&Al[r0*RP + c0];
            al[kc][1] = *(const unsigned*)&Al[r1*RP + c0];
            al[kc][2] = *(const unsigned*)&Al[r0*RP + c1];
            al[kc][3] = *(const unsigned*)&Al[r1*RP + c1];
        }
        __syncthreads();                 // all A reads done; writes may begin
        if (t + 1 < TT) PREF(t+1);

        // ---- 16 n-tiles: 12 mma each (3 split passes x 4 k-chunks) ----
        #pragma unroll
        for (int j = 0; j < 16; j++){
            float dA0=0,dA1=0,dA2=0,dA3=0, dB0=0,dB1=0,dB2=0,dB3=0,
                  dC0=0,dC1=0,dC2=0,dC3=0;
            #pragma unroll
            for (int kc = 0; kc < 4; kc++){
                int off = ((kc*16 + j)*32 + lane)*2;
                uint2 bh = *(const uint2*)(BfH + off);
                uint2 bl = *(const uint2*)(BfL + off);
                MMA(dA0,dA1,dA2,dA3, ah[kc][0],ah[kc][1],ah[kc][2],ah[kc][3], bh.x, bh.y);
                MMA(dB0,dB1,dB2,dB3, al[kc][0],al[kc][1],al[kc][2],al[kc][3], bh.x, bh.y);
                MMA(dC0,dC1,dC2,dC3, ah[kc][0],ah[kc][1],ah[kc][2],ah[kc][3], bl.x, bl.y);
            }
            float d0 = dA0 + dB0 + dC0;
            float d1 = dA1 + dB1 + dC1;
            float d2 = dA2 + dB2 + dC2;
            float d3 = dA3 + dB3 + dC3;

            // epilogue: even lanes hold (r,z), odd (nx,nh); rows g / g+8.
            int u = 2*j + uc;
            float4 bb = *(const float4*)(sbias + u*4);
            float s1v = even ? d2 : d0;
            float x1  = __shfl_xor_sync(0xffffffffu, s1v, 1);
            float s2v = even ? d3 : d1;
            float x2  = __shfl_xor_sync(0xffffffffu, s2v, 1);
            float vr  = even ? d0 : x1;
            float vz  = even ? d1 : x2;
            float vnx = even ? x1 : d2;
            float vnh = even ? x2 : d3;
            float rr = sigmf(vr + bb.x);
            float zz = sigmf(vz + bb.y);
            float nn = tanh_fast(vnx + bb.z + rr*(vnh + bb.w));
            float hn = nn + zz*(hreg[j] - nn);
            hreg[j] = hn;
            __nv_bfloat16 hh = __float2bfloat16(hn);
            Ah[hrow*RP + 32 + u] = hh;
            Al[hrow*RP + 32 + u] = __float2bfloat16(hn - __bfloat162float(hh));
        }
        if (t + 1 < TT) XSTORE;
        __syncthreads();                 // A(t+1) complete
    }

    // ---- final projection: h(64x32) @ Wo(32x16) ----
    float* Hout = (float*)(sm + OFF_BFH);     // reuse B-frag space: [64][33] f32
    #pragma unroll
    for (int j = 0; j < 16; j++)
        Hout[hrow*33 + 2*j + uc] = hreg[j];
    __syncthreads();
    {
        int ss = tid >> 1, jo = (tid & 1)*8;
        float o[8];
        #pragma unroll
        for (int j2 = 0; j2 < 8; j2++) o[j2] = 0.0f;
        #pragma unroll 8
        for (int u = 0; u < 32; u++){
            float hv = Hout[ss*33 + u];
            #pragma unroll
            for (int j2 = 0; j2 < 8; j2++)
                o[j2] = fmaf(hv, swo[u*16 + jo + j2], o[j2]);
        }
        float* op = out + ((size_t)(seqbase + ss))*16 + jo;
        #pragma unroll
        for (int j2 = 0; j2 < 8; j2++) op[j2] = o[j2];
    }
}

extern "C" void kernel_launch(void* const* d_in, const int* in_sizes, int n_in,
                              void* d_out, int out_size)
{
    const float* spat = (const float*)d_in[0];
    const float* met  = (const float*)d_in[1];
    const float* ctx  = (const float*)d_in[2];
    const float* W_ih = (const float*)d_in[3];
    const float* W_hh = (const float*)d_in[4];
    const float* b_ih = (const float*)d_in[5];
    const float* b_hh = (const float*)d_in[6];
    const float* Wo   = (const float*)d_in[7];
    float* out = (float*)d_out;

    cudaFuncSetAttribute(gru_tc, cudaFuncAttributeMaxDynamicSharedMemorySize, SMEM_BYTES);
    dim3 grid(NSEQ / 64);   // 1024 CTAs x 128 threads, 64 seqs/CTA
    gru_tc<<<grid, NT, SMEM_BYTES>>>(spat, met, ctx, W_ih, W_hh, b_ih, b_hh, Wo, out);
}

// round 10
// speedup vs baseline: 3.5913x; 1.2959x over previous
#include <cuda_runtime.h>
#include <cuda_bf16.h>

// TemporalViewModel GRU via bf16 split-precision tensor-core GEMM, gate-major.
// Per step: A=[x|h] (64 seqs x 64 K) @ B (64 x 128), cols GATE-MAJOR:
// col = gate*32 + u (gate 0=r,1=z,2=nx,3=nh). n-tiles are gate-pure, so
// nx tiles only need k-chunks 0-1 (x half) and nh only 2-3 (h half):
// 144 mma/warp/step instead of 192, and the epilogue needs NO shuffles —
// each thread ends up with r,z,nx,nh for the same (row, unit) in registers.
// Split precision: w = hi+lo bf16; D = Ahi*Bhi + (Alo*Bhi + Ahi*Blo), fp32 acc.

#define TT   24
#define NSEQ 65536
#define NT   128
#define RP   72          // A row pitch (bf16); 144 B -> conflict-free frags

// SMEM byte offsets
#define OFF_AH   0                    // Ahi [64][RP] bf16    9216 B
#define OFF_AL   9216                 // Alo                  9216 B
#define OFF_BFH  18432                // B frags hi: 48 chunks x 64 u32 = 12288 B
#define OFF_BFL  30720                // B frags lo           12288 B
#define OFF_BIAS 43008                // bias [gate][32] f32    512 B
#define OFF_WO   43520                // proj W 32x16 f32      2048 B
#define SMEM_BYTES 45568

__device__ __forceinline__ float sigmf(float x){
    return __fdividef(1.0f, 1.0f + __expf(-x));
}
__device__ __forceinline__ float tanh_fast(float x){
    x = fminf(fmaxf(x, -15.0f), 15.0f);
    float e = __expf(2.0f * x);
    return (e - 1.0f) * __fdividef(1.0f, e + 1.0f);
}
__device__ __forceinline__ unsigned pk_bf2(float a, float b){
    __nv_bfloat162 t = __floats2bfloat162_rn(a, b);
    return *(unsigned*)&t;
}
// weight at K-row k for gate-major column col (gate = col>>5, u = col&31)
__device__ __forceinline__ float wlook2(int k, int col,
        const float* __restrict__ Wih, const float* __restrict__ Whh){
    int g2 = col >> 5, u = col & 31;
    if (k < 32){
        if (g2 == 3) return 0.0f;
        return Wih[(g2*32 + u)*32 + k];
    }
    if (g2 == 2) return 0.0f;
    int row = (g2 == 3) ? (64 + u) : (g2*32 + u);
    return Whh[row*32 + (k - 32)];
}

#define MMA(d0,d1,d2,d3,a0,a1,a2,a3,b0,b1) \
  asm volatile("mma.sync.aligned.m16n8k16.row.col.f32.bf16.bf16.f32 " \
    "{%0,%1,%2,%3}, {%4,%5,%6,%7}, {%8,%9}, {%0,%1,%2,%3};" \
    : "+f"(d0),"+f"(d1),"+f"(d2),"+f"(d3) \
    : "r"(a0),"r"(a1),"r"(a2),"r"(a3),"r"(b0),"r"(b1))
#define MMA4(d,a,b) MMA(d[0],d[1],d[2],d[3], a[0],a[1],a[2],a[3], b.x, b.y)

#define PREF(tt) { size_t b_ = ((size_t)(tt)*NSEQ + seqbase + s); \
    if (half == 0){ const float4* q = (const float4*)(spat + b_*16); \
      pf0=q[0]; pf1=q[1]; pf2=q[2]; pf3=q[3]; } \
    else { const float4* qm = (const float4*)(met + b_*8); \
           const float4* qc = (const float4*)(ctx + b_*8); \
      pf0=qm[0]; pf1=qm[1]; pf2=qc[0]; pf3=qc[1]; } }

#define XSTORE { float c4[16]; \
    *(float4*)(c4+0)=pf0; *(float4*)(c4+4)=pf1; *(float4*)(c4+8)=pf2; *(float4*)(c4+12)=pf3; \
    _Pragma("unroll") \
    for (int q = 0; q < 8; q++){ \
      float v0 = c4[2*q], v1 = c4[2*q+1]; \
      float l0 = v0 - __bfloat162float(__float2bfloat16(v0)); \
      float l1 = v1 - __bfloat162float(__float2bfloat16(v1)); \
      *(unsigned*)&Ah[s*RP + kb + 2*q] = pk_bf2(v0, v1); \
      *(unsigned*)&Al[s*RP + kb + 2*q] = pk_bf2(l0, l1); } }

extern "C" __global__ void __launch_bounds__(NT, 5)
gru_tc(const float* __restrict__ spat, const float* __restrict__ met,
       const float* __restrict__ ctx,
       const float* __restrict__ W_ih, const float* __restrict__ W_hh,
       const float* __restrict__ b_ih, const float* __restrict__ b_hh,
       const float* __restrict__ Wo, float* __restrict__ out)
{
    extern __shared__ char sm[];
    __nv_bfloat16* Ah = (__nv_bfloat16*)(sm + OFF_AH);
    __nv_bfloat16* Al = (__nv_bfloat16*)(sm + OFF_AL);
    unsigned* BfH = (unsigned*)(sm + OFF_BFH);
    unsigned* BfL = (unsigned*)(sm + OFF_BFL);
    float* sbias = (float*)(sm + OFF_BIAS);
    float* swo   = (float*)(sm + OFF_WO);

    const int tid = threadIdx.x;
    const int lane = tid & 31, wrp = tid >> 5;
    const int R = wrp * 16;
    const int seqbase = blockIdx.x * 64;

    // ---- prologue ----
    { unsigned* az = (unsigned*)sm;                    // zero Ahi+Alo
      for (int i = tid; i < 4608; i += NT) az[i] = 0; }

    // B fragments in mainloop read order. Chunk map (48 chunks x 64 u32):
    //  [0,16):  r  tiles j=0..3,  kc=0..3   chunk = j*4 + kc
    //  [16,32): z  tiles j=4..7,  kc=0..3   chunk = 16 + (j-4)*4 + kc
    //  [32,40): nx tiles j=8..11, kc=0..1   chunk = 32 + (j-8)*2 + kc
    //  [40,48): nh tiles j=12..15,kc=2..3   chunk = 40 + (j-12)*2 + (kc-2)
    for (int e = tid; e < 3072; e += NT){
        int chunk = e >> 6, ln = (e >> 1) & 31, reg = e & 1;
        int j, kc;
        if (chunk < 16){ j = chunk >> 2;               kc = chunk & 3; }
        else if (chunk < 32){ int c = chunk-16; j = 4 + (c >> 2); kc = c & 3; }
        else if (chunk < 40){ int c = chunk-32; j = 8 + (c >> 1); kc = c & 1; }
        else {                int c = chunk-40; j = 12 + (c >> 1); kc = 2 + (c & 1); }
        int col = j*8 + (ln >> 2);
        int k0 = kc*16 + 2*(ln & 3) + 8*reg;
        float w0 = wlook2(k0,   col, W_ih, W_hh);
        float w1 = wlook2(k0+1, col, W_ih, W_hh);
        float h0 = __bfloat162float(__float2bfloat16(w0));
        float h1 = __bfloat162float(__float2bfloat16(w1));
        BfH[e] = pk_bf2(w0, w1);
        BfL[e] = pk_bf2(w0 - h0, w1 - h1);
    }
    if (tid < 32){
        sbias[tid]      = b_ih[tid]    + b_hh[tid];      // r
        sbias[32 + tid] = b_ih[32+tid] + b_hh[32+tid];   // z
        sbias[64 + tid] = b_ih[64+tid];                  // nx
        sbias[96 + tid] = b_hh[64+tid];                  // nh
    }
    for (int i = tid; i < 512; i += NT) swo[i] = Wo[i];

    // x(0) load + store
    const int s = tid >> 1, half = tid & 1, kb = half * 16;
    float4 pf0, pf1, pf2, pf3;
    PREF(0); XSTORE;

    float hreg[16];
    #pragma unroll
    for (int j = 0; j < 16; j++) hreg[j] = 0.0f;
    __syncthreads();

    const int g = lane >> 2, tig = lane & 3;
    const int r0 = R + g, r1 = r0 + 8;
    const int cpair = tig * 2;
    const uint2* BH2 = (const uint2*)(sm + OFF_BFH);
    const uint2* BL2 = (const uint2*)(sm + OFF_BFL);

    for (int t = 0; t < TT; t++){
        // ---- A fragments (x hi/lo + h hi/lo), reused by all 4 unit groups ----
        unsigned ah[4][4], al[4][4];
        #pragma unroll
        for (int kc = 0; kc < 4; kc++){
            int c0 = kc*16 + 2*tig, c1 = c0 + 8;
            ah[kc][0] = *(const unsigned*)&Ah[r0*RP + c0];
            ah[kc][1] = *(const unsigned*)&Ah[r1*RP + c0];
            ah[kc][2] = *(const unsigned*)&Ah[r0*RP + c1];
            ah[kc][3] = *(const unsigned*)&Ah[r1*RP + c1];
            al[kc][0] = *(const unsigned*)&Al[r0*RP + c0];
            al[kc][1] = *(const unsigned*)&Al[r1*RP + c0];
            al[kc][2] = *(const unsigned*)&Al[r0*RP + c1];
            al[kc][3] = *(const unsigned*)&Al[r1*RP + c1];
        }
        __syncthreads();                 // all A reads done; writes may begin
        if (t + 1 < TT) PREF(t+1);

        // ---- 4 unit groups x {r,z,nx,nh} tiles ----
        #pragma unroll
        for (int ug = 0; ug < 4; ug++){
            float aR[4]={0,0,0,0}, cR[4]={0,0,0,0};
            float aZ[4]={0,0,0,0}, cZ[4]={0,0,0,0};
            float aX[4]={0,0,0,0}, cX[4]={0,0,0,0};
            float aN[4]={0,0,0,0}, cN[4]={0,0,0,0};
            #pragma unroll
            for (int kc = 0; kc < 4; kc++){
                { uint2 bh = BH2[(ug*4 + kc)*32 + lane];
                  uint2 bl = BL2[(ug*4 + kc)*32 + lane];
                  MMA4(aR, ah[kc], bh); MMA4(cR, al[kc], bh); MMA4(cR, ah[kc], bl); }
                { uint2 bh = BH2[(16 + ug*4 + kc)*32 + lane];
                  uint2 bl = BL2[(16 + ug*4 + kc)*32 + lane];
                  MMA4(aZ, ah[kc], bh); MMA4(cZ, al[kc], bh); MMA4(cZ, ah[kc], bl); }
                if (kc < 2){
                  uint2 bh = BH2[(32 + ug*2 + kc)*32 + lane];
                  uint2 bl = BL2[(32 + ug*2 + kc)*32 + lane];
                  MMA4(aX, ah[kc], bh); MMA4(cX, al[kc], bh); MMA4(cX, ah[kc], bl);
                } else {
                  uint2 bh = BH2[(40 + ug*2 + kc - 2)*32 + lane];
                  uint2 bl = BL2[(40 + ug*2 + kc - 2)*32 + lane];
                  MMA4(aN, ah[kc], bh); MMA4(cN, al[kc], bh); MMA4(cN, ah[kc], bl);
                }
            }
            // ---- epilogue: no shuffles; thread owns (rows r0,r1) x (units u0,u0+1) ----
            int u0 = ug*8 + cpair;
            float2 br = *(const float2*)(sbias + u0);
            float2 bz = *(const float2*)(sbias + 32 + u0);
            float2 bx = *(const float2*)(sbias + 64 + u0);
            float2 bn = *(const float2*)(sbias + 96 + u0);
            float hn[4];
            #pragma unroll
            for (int q = 0; q < 4; q++){
                float bru = (q & 1) ? br.y : br.x;
                float bzu = (q & 1) ? bz.y : bz.x;
                float bxu = (q & 1) ? bx.y : bx.x;
                float bnu = (q & 1) ? bn.y : bn.x;
                float rr = sigmf(aR[q] + cR[q] + bru);
                float zz = sigmf(aZ[q] + cZ[q] + bzu);
                float nn = tanh_fast(aX[q] + cX[q] + bxu + rr*(aN[q] + cN[q] + bnu));
                float hv = nn + zz*(hreg[ug*4 + q] - nn);
                hreg[ug*4 + q] = hv;
                hn[q] = hv;
            }
            float l0 = hn[0] - __bfloat162float(__float2bfloat16(hn[0]));
            float l1 = hn[1] - __bfloat162float(__float2bfloat16(hn[1]));
            float l2 = hn[2] - __bfloat162float(__float2bfloat16(hn[2]));
            float l3 = hn[3] - __bfloat162float(__float2bfloat16(hn[3]));
            *(unsigned*)&Ah[r0*RP + 32 + u0] = pk_bf2(hn[0], hn[1]);
            *(unsigned*)&Ah[r1*RP + 32 + u0] = pk_bf2(hn[2], hn[3]);
            *(unsigned*)&Al[r0*RP + 32 + u0] = pk_bf2(l0, l1);
            *(unsigned*)&Al[r1*RP + 32 + u0] = pk_bf2(l2, l3);
        }
        if (t + 1 < TT) XSTORE;
        __syncthreads();                 // A(t+1) complete
    }

    // ---- final projection: h(64x32) @ Wo(32x16) ----
    float* Hout = (float*)(sm + OFF_BFH);     // reuse B-frag space: [64][33] f32
    #pragma unroll
    for (int ug = 0; ug < 4; ug++){
        int u0 = ug*8 + cpair;
        Hout[r0*33 + u0]     = hreg[ug*4 + 0];
        Hout[r0*33 + u0 + 1] = hreg[ug*4 + 1];
        Hout[r1*33 + u0]     = hreg[ug*4 + 2];
        Hout[r1*33 + u0 + 1] = hreg[ug*4 + 3];
    }
    __syncthreads();
    {
        int ss = tid >> 1, jo = (tid & 1)*8;
        float o[8];
        #pragma unroll
        for (int j2 = 0; j2 < 8; j2++) o[j2] = 0.0f;
        #pragma unroll 8
        for (int u = 0; u < 32; u++){
            float hv = Hout[ss*33 + u];
            #pragma unroll
            for (int j2 = 0; j2 < 8; j2++)
                o[j2] = fmaf(hv, swo[u*16 + jo + j2], o[j2]);
        }
        float* op = out + ((size_t)(seqbase + ss))*16 + jo;
        #pragma unroll
        for (int j2 = 0; j2 < 8; j2++) op[j2] = o[j2];
    }
}

extern "C" void kernel_launch(void* const* d_in, const int* in_sizes, int n_in,
                              void* d_out, int out_size)
{
    const float* spat = (const float*)d_in[0];
    const float* met  = (const float*)d_in[1];
    const float* ctx  = (const float*)d_in[2];
    const float* W_ih = (const float*)d_in[3];
    const float* W_hh = (const float*)d_in[4];
    const float* b_ih = (const float*)d_in[5];
    const float* b_hh = (const float*)d_in[6];
    const float* Wo   = (const float*)d_in[7];
    float* out = (float*)d_out;

    cudaFuncSetAttribute(gru_tc, cudaFuncAttributeMaxDynamicSharedMemorySize, SMEM_BYTES);
    dim3 grid(NSEQ / 64);   // 1024 CTAs x 128 threads, 64 seqs/CTA
    gru_tc<<<grid, NT, SMEM_BYTES>>>(spat, met, ctx, W_ih, W_hh, b_ih, b_hh, Wo, out);
}

// round 13
// speedup vs baseline: 3.6295x; 1.0106x over previous
#include <cuda_runtime.h>
#include <cuda_bf16.h>

// TemporalViewModel GRU via bf16 split-precision tensor-core GEMM, gate-major.
// Per step: A=[x|h] (64 seqs x 64 K) @ B (64 x 128), cols GATE-MAJOR:
// col = gate*32 + u (gate 0=r,1=z,2=nx,3=nh). n-tiles are gate-pure, so
// nx tiles only need k-chunks 0-1 (x half) and nh only 2-3 (h half):
// 144 mma/warp/step instead of 192, and the epilogue needs NO shuffles —
// each thread ends up with r,z,nx,nh for the same (row, unit) in registers.
// Split precision: w = hi+lo bf16; D = Ahi*Bhi + (Alo*Bhi + Ahi*Blo), fp32 acc.

#define TT   24
#define NSEQ 65536
#define NT   128
#define RP   72          // A row pitch (bf16); 144 B -> conflict-free frags

// SMEM byte offsets
#define OFF_AH   0                    // Ahi [64][RP] bf16    9216 B
#define OFF_AL   9216                 // Alo                  9216 B
#define OFF_BFH  18432                // B frags hi: 48 chunks x 64 u32 = 12288 B
#define OFF_BFL  30720                // B frags lo           12288 B
#define OFF_BIAS 43008                // bias [gate][32] f32    512 B
#define OFF_WO   43520                // proj W 32x16 f32      2048 B
#define SMEM_BYTES 45568

__device__ __forceinline__ float sigmf(float x){
    return __fdividef(1.0f, 1.0f + __expf(-x));
}
__device__ __forceinline__ float tanh_fast(float x){
    x = fminf(fmaxf(x, -15.0f), 15.0f);
    float e = __expf(2.0f * x);
    return (e - 1.0f) * __fdividef(1.0f, e + 1.0f);
}
__device__ __forceinline__ unsigned pk_bf2(float a, float b){
    __nv_bfloat162 t = __floats2bfloat162_rn(a, b);
    return *(unsigned*)&t;
}
// weight at K-row k for gate-major column col (gate = col>>5, u = col&31)
__device__ __forceinline__ float wlook2(int k, int col,
        const float* __restrict__ Wih, const float* __restrict__ Whh){
    int g2 = col >> 5, u = col & 31;
    if (k < 32){
        if (g2 == 3) return 0.0f;
        return Wih[(g2*32 + u)*32 + k];
    }
    if (g2 == 2) return 0.0f;
    int row = (g2 == 3) ? (64 + u) : (g2*32 + u);
    return Whh[row*32 + (k - 32)];
}

#define MMA(d0,d1,d2,d3,a0,a1,a2,a3,b0,b1) \
  asm volatile("mma.sync.aligned.m16n8k16.row.col.f32.bf16.bf16.f32 " \
    "{%0,%1,%2,%3}, {%4,%5,%6,%7}, {%8,%9}, {%0,%1,%2,%3};" \
    : "+f"(d0),"+f"(d1),"+f"(d2),"+f"(d3) \
    : "r"(a0),"r"(a1),"r"(a2),"r"(a3),"r"(b0),"r"(b1))
#define MMA4(d,a,b) MMA(d[0],d[1],d[2],d[3], a[0],a[1],a[2],a[3], b.x, b.y)

#define PREF(tt) { size_t b_ = ((size_t)(tt)*NSEQ + seqbase + s); \
    if (half == 0){ const float4* q = (const float4*)(spat + b_*16); \
      pf0=q[0]; pf1=q[1]; pf2=q[2]; pf3=q[3]; } \
    else { const float4* qm = (const float4*)(met + b_*8); \
           const float4* qc = (const float4*)(ctx + b_*8); \
      pf0=qm[0]; pf1=qm[1]; pf2=qc[0]; pf3=qc[1]; } }

#define XSTORE { float c4[16]; \
    *(float4*)(c4+0)=pf0; *(float4*)(c4+4)=pf1; *(float4*)(c4+8)=pf2; *(float4*)(c4+12)=pf3; \
    _Pragma("unroll") \
    for (int q = 0; q < 8; q++){ \
      float v0 = c4[2*q], v1 = c4[2*q+1]; \
      float l0 = v0 - __bfloat162float(__float2bfloat16(v0)); \
      float l1 = v1 - __bfloat162float(__float2bfloat16(v1)); \
      *(unsigned*)&Ah[s*RP + kb + 2*q] = pk_bf2(v0, v1); \
      *(unsigned*)&Al[s*RP + kb + 2*q] = pk_bf2(l0, l1); } }

extern "C" __global__ void __launch_bounds__(NT, 5)
gru_tc(const float* __restrict__ spat, const float* __restrict__ met,
       const float* __restrict__ ctx,
       const float* __restrict__ W_ih, const float* __restrict__ W_hh,
       const float* __restrict__ b_ih, const float* __restrict__ b_hh,
       const float* __restrict__ Wo, float* __restrict__ out)
{
    extern __shared__ char sm[];
    __nv_bfloat16* Ah = (__nv_bfloat16*)(sm + OFF_AH);
    __nv_bfloat16* Al = (__nv_bfloat16*)(sm + OFF_AL);
    unsigned* BfH = (unsigned*)(sm + OFF_BFH);
    unsigned* BfL = (unsigned*)(sm + OFF_BFL);
    float* sbias = (float*)(sm + OFF_BIAS);
    float* swo   = (float*)(sm + OFF_WO);

    const int tid = threadIdx.x;
    const int lane = tid & 31, wrp = tid >> 5;
    const int R = wrp * 16;
    const int seqbase = blockIdx.x * 64;

    // ---- prologue ----
    { unsigned* az = (unsigned*)sm;                    // zero Ahi+Alo
      for (int i = tid; i < 4608; i += NT) az[i] = 0; }

    // B fragments in mainloop read order. Chunk map (48 chunks x 64 u32):
    //  [0,16):  r  tiles j=0..3,  kc=0..3   chunk = j*4 + kc
    //  [16,32): z  tiles j=4..7,  kc=0..3   chunk = 16 + (j-4)*4 + kc
    //  [32,40): nx tiles j=8..11, kc=0..1   chunk = 32 + (j-8)*2 + kc
    //  [40,48): nh tiles j=12..15,kc=2..3   chunk = 40 + (j-12)*2 + (kc-2)
    for (int e = tid; e < 3072; e += NT){
        int chunk = e >> 6, ln = (e >> 1) & 31, reg = e & 1;
        int j, kc;
        if (chunk < 16){ j = chunk >> 2;               kc = chunk & 3; }
        else if (chunk < 32){ int c = chunk-16; j = 4 + (c >> 2); kc = c & 3; }
        else if (chunk < 40){ int c = chunk-32; j = 8 + (c >> 1); kc = c & 1; }
        else {                int c = chunk-40; j = 12 + (c >> 1); kc = 2 + (c & 1); }
        int col = j*8 + (ln >> 2);
        int k0 = kc*16 + 2*(ln & 3) + 8*reg;
        float w0 = wlook2(k0,   col, W_ih, W_hh);
        float w1 = wlook2(k0+1, col, W_ih, W_hh);
        float h0 = __bfloat162float(__float2bfloat16(w0));
        float h1 = __bfloat162float(__float2bfloat16(w1));
        BfH[e] = pk_bf2(w0, w1);
        BfL[e] = pk_bf2(w0 - h0, w1 - h1);
    }
    if (tid < 32){
        sbias[tid]      = b_ih[tid]    + b_hh[tid];      // r
        sbias[32 + tid] = b_ih[32+tid] + b_hh[32+tid];   // z
        sbias[64 + tid] = b_ih[64+tid];                  // nx
        sbias[96 + tid] = b_hh[64+tid];                  // nh
    }
    for (int i = tid; i < 512; i += NT) swo[i] = Wo[i];

    // x(0) load + store
    const int s = tid >> 1, half = tid & 1, kb = half * 16;
    float4 pf0, pf1, pf2, pf3;
    PREF(0); XSTORE;

    float hreg[16];
    #pragma unroll
    for (int j = 0; j < 16; j++) hreg[j] = 0.0f;
    __syncthreads();

    const int g = lane >> 2, tig = lane & 3;
    const int r0 = R + g, r1 = r0 + 8;
    const int cpair = tig * 2;
    const uint2* BH2 = (const uint2*)(sm + OFF_BFH);
    const uint2* BL2 = (const uint2*)(sm + OFF_BFL);

    for (int t = 0; t < TT; t++){
        // ---- A fragments (x hi/lo + h hi/lo), reused by all 4 unit groups ----
        unsigned ah[4][4], al[4][4];
        #pragma unroll
        for (int kc = 0; kc < 4; kc++){
            int c0 = kc*16 + 2*tig, c1 = c0 + 8;
            ah[kc][0] = *(const unsigned*)&Ah[r0*RP + c0];
            ah[kc][1] = *(const unsigned*)&Ah[r1*RP + c0];
            ah[kc][2] = *(const unsigned*)&Ah[r0*RP + c1];
            ah[kc][3] = *(const unsigned*)&Ah[r1*RP + c1];
            al[kc][0] = *(const unsigned*)&Al[r0*RP + c0];
            al[kc][1] = *(const unsigned*)&Al[r1*RP + c0];
            al[kc][2] = *(const unsigned*)&Al[r0*RP + c1];
            al[kc][3] = *(const unsigned*)&Al[r1*RP + c1];
        }
        __syncthreads();                 // all A reads done; writes may begin
        if (t + 1 < TT) PREF(t+1);

        // ---- 4 unit groups x {r,z,nx,nh} tiles ----
        #pragma unroll
        for (int ug = 0; ug < 4; ug++){
            float aR[4]={0,0,0,0}, cR[4]={0,0,0,0};
            float aZ[4]={0,0,0,0}, cZ[4]={0,0,0,0};
            float aX[4]={0,0,0,0}, cX[4]={0,0,0,0};
            float aN[4]={0,0,0,0}, cN[4]={0,0,0,0};
            #pragma unroll
            for (int kc = 0; kc < 4; kc++){
                { uint2 bh = BH2[(ug*4 + kc)*32 + lane];
                  uint2 bl = BL2[(ug*4 + kc)*32 + lane];
                  MMA4(aR, ah[kc], bh); MMA4(cR, al[kc], bh); MMA4(cR, ah[kc], bl); }
                { uint2 bh = BH2[(16 + ug*4 + kc)*32 + lane];
                  uint2 bl = BL2[(16 + ug*4 + kc)*32 + lane];
                  MMA4(aZ, ah[kc], bh); MMA4(cZ, al[kc], bh); MMA4(cZ, ah[kc], bl); }
                if (kc < 2){
                  uint2 bh = BH2[(32 + ug*2 + kc)*32 + lane];
                  uint2 bl = BL2[(32 + ug*2 + kc)*32 + lane];
                  MMA4(aX, ah[kc], bh); MMA4(cX, al[kc], bh); MMA4(cX, ah[kc], bl);
                } else {
                  uint2 bh = BH2[(40 + ug*2 + kc - 2)*32 + lane];
                  uint2 bl = BL2[(40 + ug*2 + kc - 2)*32 + lane];
                  MMA4(aN, ah[kc], bh); MMA4(cN, al[kc], bh); MMA4(cN, ah[kc], bl);
                }
            }
            // ---- epilogue: no shuffles; thread owns (rows r0,r1) x (units u0,u0+1) ----
            int u0 = ug*8 + cpair;
            float2 br = *(const float2*)(sbias + u0);
            float2 bz = *(const float2*)(sbias + 32 + u0);
            float2 bx = *(const float2*)(sbias + 64 + u0);
            float2 bn = *(const float2*)(sbias + 96 + u0);
            float hn[4];
            #pragma unroll
            for (int q = 0; q < 4; q++){
                float bru = (q & 1) ? br.y : br.x;
                float bzu = (q & 1) ? bz.y : bz.x;
                float bxu = (q & 1) ? bx.y : bx.x;
                float bnu = (q & 1) ? bn.y : bn.x;
                float rr = sigmf(aR[q] + cR[q] + bru);
                float zz = sigmf(aZ[q] + cZ[q] + bzu);
                float nn = tanh_fast(aX[q] + cX[q] + bxu + rr*(aN[q] + cN[q] + bnu));
                float hv = nn + zz*(hreg[ug*4 + q] - nn);
                hreg[ug*4 + q] = hv;
                hn[q] = hv;
            }
            float l0 = hn[0] - __bfloat162float(__float2bfloat16(hn[0]));
            float l1 = hn[1] - __bfloat162float(__float2bfloat16(hn[1]));
            float l2 = hn[2] - __bfloat162float(__float2bfloat16(hn[2]));
            float l3 = hn[3] - __bfloat162float(__float2bfloat16(hn[3]));
            *(unsigned*)&Ah[r0*RP + 32 + u0] = pk_bf2(hn[0], hn[1]);
            *(unsigned*)&Ah[r1*RP + 32 + u0] = pk_bf2(hn[2], hn[3]);
            *(unsigned*)&Al[r0*RP + 32 + u0] = pk_bf2(l0, l1);
            *(unsigned*)&Al[r1*RP + 32 + u0] = pk_bf2(l2, l3);
        }
        if (t + 1 < TT) XSTORE;
        __syncthreads();                 // A(t+1) complete
    }

    // ---- final projection: h(64x32) @ Wo(32x16) ----
    float* Hout = (float*)(sm + OFF_BFH);     // reuse B-frag space: [64][33] f32
    #pragma unroll
    for (int ug = 0; ug < 4; ug++){
        int u0 = ug*8 + cpair;
        Hout[r0*33 + u0]     = hreg[ug*4 + 0];
        Hout[r0*33 + u0 + 1] = hreg[ug*4 + 1];
        Hout[r1*33 + u0]     = hreg[ug*4 + 2];
        Hout[r1*33 + u0 + 1] = hreg[ug*4 + 3];
    }
    __syncthreads();
    {
        int ss = tid >> 1, jo = (tid & 1)*8;
        float o[8];
        #pragma unroll
        for (int j2 = 0; j2 < 8; j2++) o[j2] = 0.0f;
        #pragma unroll 8
        for (int u = 0; u < 32; u++){
            float hv = Hout[ss*33 + u];
            #pragma unroll
            for (int j2 = 0; j2 < 8; j2++)
                o[j2] = fmaf(hv, swo[u*16 + jo + j2], o[j2]);
        }
        float* op = out + ((size_t)(seqbase + ss))*16 + jo;
        #pragma unroll
        for (int j2 = 0; j2 < 8; j2++) op[j2] = o[j2];
    }
}

extern "C" void kernel_launch(void* const* d_in, const int* in_sizes, int n_in,
                              void* d_out, int out_size)
{
    const float* spat = (const float*)d_in[0];
    const float* met  = (const float*)d_in[1];
    const float* ctx  = (const float*)d_in[2];
    const float* W_ih = (const float*)d_in[3];
    const float* W_hh = (const float*)d_in[4];
    const float* b_ih = (const float*)d_in[5];
    const float* b_hh = (const float*)d_in[6];
    const float* Wo   = (const float*)d_in[7];
    float* out = (float*)d_out;

    cudaFuncSetAttribute(gru_tc, cudaFuncAttributeMaxDynamicSharedMemorySize, SMEM_BYTES);
    dim3 grid(NSEQ / 64);   // 1024 CTAs x 128 threads, 64 seqs/CTA
    gru_tc<<<grid, NT, SMEM_BYTES>>>(spat, met, ctx, W_ih, W_hh, b_ih, b_hh, Wo, out);
}